// round 3
// baseline (speedup 1.0000x reference)
#include <cuda_runtime.h>
#include <cuda_bf16.h>
#include <math.h>

// Problem shapes (fixed by the dataset)
#define B_   4096
#define L_   200
#define D_   256
#define NBLK 256
#define BN_EPS 1e-5f

// -------- persistent scratch (no allocations allowed) --------
__device__ float g_pooled[B_ * D_];          // 4 MB
__device__ float g_z[B_ * D_];               // 4 MB
__device__ float g_part[2 * 64 * D_];        // per-bm-tile col sums / sumsq
__device__ float g_lossp[NBLK];              // per-block loss partials
__device__ unsigned int g_syncc[4];          // monotonic grid-sync counters

// ------------------------------------------------------------
// Monotonic grid barrier: works across graph replays without reset.
// All 256 blocks are co-resident (grid 256 <= 2/SM * 148 = 296).
// ------------------------------------------------------------
__device__ __forceinline__ void gsync(int idx)
{
    __syncthreads();
    __threadfence();                       // publish this thread's writes
    if (threadIdx.x == 0) {
        unsigned int my     = atomicAdd(&g_syncc[idx], 1u);
        unsigned int target = (my / NBLK + 1u) * NBLK;
        while (atomicAdd(&g_syncc[idx], 0u) < target)
            __nanosleep(64);
        __threadfence();
    }
    __syncthreads();
}

// ============================================================
// ONE persistent kernel: pool -> GEMM(+stats) -> head -> loss
// ============================================================
__global__ void __launch_bounds__(256, 2) fused_kernel(
    const int*   __restrict__ tokens,
    const int*   __restrict__ lengths,
    const float* __restrict__ t,
    const float* __restrict__ emb,
    const float* __restrict__ W1,
    const float* __restrict__ b1,
    const float* __restrict__ gamma,
    const float* __restrict__ beta,
    const float* __restrict__ w2,
    const float* __restrict__ b2,
    float* __restrict__ out)
{
    __shared__ union {
        int tok[16 * L_];                                   // pool: 12.8 KB
        struct { float As[64][68]; float Bs[64][68]; } g;   // gemm: 34.8 KB
        struct { float s_g[D_]; float s_be[D_]; float s_w[D_]; float red[8]; } h;
    } sm;

    const int tid = threadIdx.x;
    const int bid = blockIdx.x;

    // ================= Phase 1: ragged gather + mean pool =================
    // 16 rows per block. Threads split into 2 row-groups of 128 threads;
    // each thread owns a float2 dim-pair -> half the LDG count, 2x MLP.
    {
        const int base = bid * 16 * L_;
        for (int i = tid; i < 16 * L_; i += 256)
            sm.tok[i] = tokens[base + i];
        __syncthreads();

        const int half = tid >> 7;          // 0 or 1 (row group)
        const int htid = tid & 127;         // dim-pair index
        const float2* __restrict__ emb2 = (const float2*)emb;
        float2* pooled2 = (float2*)g_pooled;

        #pragma unroll 1
        for (int rr = 0; rr < 8; ++rr) {
            const int r_loc = rr * 2 + half;
            const int row   = bid * 16 + r_loc;
            const int len   = lengths[row];
            const int* tk   = &sm.tok[r_loc * L_];

            float2 a0 = make_float2(0.f, 0.f);
            float2 a1 = make_float2(0.f, 0.f);
            int l = 0;
            for (; l + 8 <= len; l += 8) {
                float2 v0 = emb2[(size_t)tk[l + 0] * 128 + htid];
                float2 v1 = emb2[(size_t)tk[l + 1] * 128 + htid];
                float2 v2 = emb2[(size_t)tk[l + 2] * 128 + htid];
                float2 v3 = emb2[(size_t)tk[l + 3] * 128 + htid];
                float2 v4 = emb2[(size_t)tk[l + 4] * 128 + htid];
                float2 v5 = emb2[(size_t)tk[l + 5] * 128 + htid];
                float2 v6 = emb2[(size_t)tk[l + 6] * 128 + htid];
                float2 v7 = emb2[(size_t)tk[l + 7] * 128 + htid];
                a0.x += (v0.x + v1.x) + (v2.x + v3.x);
                a0.y += (v0.y + v1.y) + (v2.y + v3.y);
                a1.x += (v4.x + v5.x) + (v6.x + v7.x);
                a1.y += (v4.y + v5.y) + (v6.y + v7.y);
            }
            for (; l < len; ++l) {
                float2 v = emb2[(size_t)tk[l] * 128 + htid];
                a0.x += v.x; a0.y += v.y;
            }
            float inv = 1.f / (float)len;
            pooled2[(size_t)row * 128 + htid] =
                make_float2((a0.x + a1.x) * inv, (a0.y + a1.y) * inv);
        }
    }

    gsync(0);

    // ================= Phase 2: Z = pooled @ W1^T + b1, fused stats ======
    // BM=BN=BK=64, 4x4 thread tiles, scalar FFMA (2 LDS.128 per kk).
    {
        const int bm = (bid >> 2) * 64;
        const int bn = (bid & 3) * 64;
        const int tx = tid & 15;
        const int ty = tid >> 4;

        float c[4][4] = {};

        for (int k0 = 0; k0 < D_; k0 += 64) {
            #pragma unroll
            for (int j = 0; j < 4; ++j) {
                int idx = tid + j * 256;
                int m   = idx >> 4;            // 0..63
                int k4  = idx & 15;            // 0..15
                float4 va = *(const float4*)&g_pooled[(size_t)(bm + m) * D_ + k0 + k4 * 4];
                sm.g.As[k4 * 4 + 0][m] = va.x; sm.g.As[k4 * 4 + 1][m] = va.y;
                sm.g.As[k4 * 4 + 2][m] = va.z; sm.g.As[k4 * 4 + 3][m] = va.w;
                float4 vb = *(const float4*)&W1[(size_t)(bn + m) * D_ + k0 + k4 * 4];
                sm.g.Bs[k4 * 4 + 0][m] = vb.x; sm.g.Bs[k4 * 4 + 1][m] = vb.y;
                sm.g.Bs[k4 * 4 + 2][m] = vb.z; sm.g.Bs[k4 * 4 + 3][m] = vb.w;
            }
            __syncthreads();

            #pragma unroll
            for (int kk = 0; kk < 64; ++kk) {
                float4 a  = *(const float4*)&sm.g.As[kk][ty * 4];
                float4 bv = *(const float4*)&sm.g.Bs[kk][tx * 4];
                float ar[4] = {a.x, a.y, a.z, a.w};
                float br[4] = {bv.x, bv.y, bv.z, bv.w};
                #pragma unroll
                for (int i = 0; i < 4; ++i)
                    #pragma unroll
                    for (int jj = 0; jj < 4; ++jj)
                        c[i][jj] = fmaf(ar[i], br[jj], c[i][jj]);
            }
            __syncthreads();
        }

        // bias + store Z + per-thread column sums/sumsq
        float s[4] = {0, 0, 0, 0}, ss[4] = {0, 0, 0, 0};
        #pragma unroll
        for (int jj = 0; jj < 4; ++jj) {
            float bias = b1[bn + tx * 4 + jj];
            #pragma unroll
            for (int i = 0; i < 4; ++i) {
                float z = c[i][jj] + bias;
                g_z[(size_t)(bm + ty * 4 + i) * D_ + bn + tx * 4 + jj] = z;
                s[jj]  += z;
                ss[jj] = fmaf(z, z, ss[jj]);
            }
        }

        // block reduction over ty (16) into g_part — reuse As storage
        float* rs  = &sm.g.As[0][0];       // [16][64] sums
        float* rss = rs + 16 * 64;         // [16][64] sumsq
        #pragma unroll
        for (int jj = 0; jj < 4; ++jj) {
            rs [ty * 64 + tx * 4 + jj] = s[jj];
            rss[ty * 64 + tx * 4 + jj] = ss[jj];
        }
        __syncthreads();
        #pragma unroll
        for (int st = 8; st >= 1; st >>= 1) {
            if (ty < st) {
                #pragma unroll
                for (int jj = 0; jj < 4; ++jj) {
                    int cc2 = tx * 4 + jj;
                    rs [ty * 64 + cc2] += rs [(ty + st) * 64 + cc2];
                    rss[ty * 64 + cc2] += rss[(ty + st) * 64 + cc2];
                }
            }
            __syncthreads();
        }
        if (ty == 0) {
            #pragma unroll
            for (int jj = 0; jj < 4; ++jj) {
                int cc2 = tx * 4 + jj;
                g_part[(bid >> 2) * D_ + bn + cc2]            = rs [cc2];
                g_part[64 * D_ + (bid >> 2) * D_ + bn + cc2]  = rss[cc2];
            }
        }
    }

    gsync(1);

    // ================= Phase 3: BN finalize + BN+ReLU+dot+BCE ============
    {
        // fold stats for dim d = tid (redundant per block; L2-broadcast)
        float smv = 0.f, sq = 0.f;
        #pragma unroll 8
        for (int rb = 0; rb < 64; ++rb) {
            smv += g_part[rb * D_ + tid];
            sq  += g_part[64 * D_ + rb * D_ + tid];
        }
        float mu   = smv * (1.f / (float)B_);
        float var  = sq  * (1.f / (float)B_) - mu * mu;
        float rstd = rsqrtf(var + BN_EPS);
        float gg   = gamma[tid] * rstd;
        sm.h.s_g[tid]  = gg;
        sm.h.s_be[tid] = beta[tid] - gg * mu;
        sm.h.s_w[tid]  = w2[tid];
        __syncthreads();

        const int lane = tid & 31;
        const int warp = tid >> 5;
        const int row0 = bid * 16 + warp * 2;   // 2 rows per warp
        const float b2v = b2[0];

        float acc[2] = {0.f, 0.f};
        #pragma unroll
        for (int k = 0; k < 8; ++k) {
            int dm = lane + 32 * k;
            float gk = sm.h.s_g[dm], bek = sm.h.s_be[dm], wk = sm.h.s_w[dm];
            #pragma unroll
            for (int r = 0; r < 2; ++r) {
                float zv = g_z[(size_t)(row0 + r) * D_ + dm];
                acc[r] += fmaxf(fmaf(gk, zv, bek), 0.f) * wk;
            }
        }
        #pragma unroll
        for (int off = 16; off > 0; off >>= 1) {
            acc[0] += __shfl_xor_sync(0xFFFFFFFFu, acc[0], off);
            acc[1] += __shfl_xor_sync(0xFFFFFFFFu, acc[1], off);
        }

        if (lane == 0) {
            float lossacc = 0.f;
            #pragma unroll
            for (int r = 0; r < 2; ++r) {
                float l = acc[r] + b2v;
                out[1 + row0 + r] = l;
                float tb = t[row0 + r];
                lossacc += fmaxf(l, 0.f) - l * tb + log1pf(expf(-fabsf(l)));
            }
            sm.h.red[warp] = lossacc;
        }
        __syncthreads();
        if (tid == 0) {
            float sum = 0.f;
            #pragma unroll
            for (int w = 0; w < 8; ++w) sum += sm.h.red[w];
            g_lossp[bid] = sum;
        }
    }

    gsync(2);

    // ================= Phase 4: final loss (block 0 only) ================
    if (bid == 0) {
        const int lane = tid & 31;
        const int warp = tid >> 5;
        float v = g_lossp[tid];
        #pragma unroll
        for (int off = 16; off > 0; off >>= 1)
            v += __shfl_xor_sync(0xFFFFFFFFu, v, off);
        if (lane == 0) sm.h.red[warp] = v;
        __syncthreads();
        if (tid == 0) {
            float sum = 0.f;
            #pragma unroll
            for (int w = 0; w < 8; ++w) sum += sm.h.red[w];
            out[0] = sum * (1.f / (float)B_);
        }
    }
}

// ============================================================
// launch: ONE kernel
// ============================================================
extern "C" void kernel_launch(void* const* d_in, const int* in_sizes, int n_in,
                              void* d_out, int out_size)
{
    const int*   tokens  = (const int*)d_in[0];
    const int*   lengths = (const int*)d_in[1];
    const float* t       = (const float*)d_in[2];
    const float* emb     = (const float*)d_in[3];
    const float* W1      = (const float*)d_in[4];
    const float* b1      = (const float*)d_in[5];
    const float* gamma   = (const float*)d_in[6];
    const float* beta    = (const float*)d_in[7];
    const float* w2      = (const float*)d_in[8];
    const float* b2      = (const float*)d_in[9];
    float* out = (float*)d_out;

    fused_kernel<<<NBLK, 256>>>(tokens, lengths, t, emb, W1, b1,
                                gamma, beta, w2, b2, out);
}

// round 4
// speedup vs baseline: 1.2414x; 1.2414x over previous
#include <cuda_runtime.h>
#include <cuda_bf16.h>
#include <math.h>

// Problem shapes (fixed by the dataset)
#define B_  4096
#define L_  200
#define D_  256
#define BN_EPS 1e-5f

// -------- scratch (no allocations allowed) --------
__device__ float g_pooled[B_ * D_];          // 4 MB
__device__ float g_z[B_ * D_];               // 4 MB
__device__ float g_part[2 * 64 * D_];        // per-bm-tile col sums / sumsq
__device__ float g_lossp[128];               // per-head-block loss partials
__device__ unsigned int g_ticket;            // monotonic last-block ticket

// ============================================================
// Kernel 1: ragged gather + mean pool.
// 1 block = 4 batch rows, 256 threads = 4 x (64 threads x float4).
// 8 float4 LDGs in flight per thread; grid 1024 for full occupancy.
// ============================================================
__global__ void __launch_bounds__(256) pool_kernel(
    const int* __restrict__ tokens,
    const int* __restrict__ lengths,
    const float* __restrict__ emb)
{
    const int b0  = blockIdx.x * 4;
    const int tid = threadIdx.x;
    __shared__ int s_tok[4 * L_];
    __shared__ int s_len[4];

    for (int i = tid; i < 4 * L_; i += 256)
        s_tok[i] = tokens[b0 * L_ + i];
    if (tid < 4) s_len[tid] = lengths[b0 + tid];
    __syncthreads();

    const int r = tid >> 6;          // row within block (0..3)
    const int q = tid & 63;          // float4 index within row (0..63)
    const int len = s_len[r];
    const int* tk = &s_tok[r * L_];
    const float4* __restrict__ emb4 = (const float4*)emb;   // row stride 64

    float4 a0 = make_float4(0.f, 0.f, 0.f, 0.f);
    float4 a1 = make_float4(0.f, 0.f, 0.f, 0.f);
    int l = 0;
    for (; l + 8 <= len; l += 8) {
        float4 v0 = __ldg(&emb4[(size_t)tk[l + 0] * 64 + q]);
        float4 v1 = __ldg(&emb4[(size_t)tk[l + 1] * 64 + q]);
        float4 v2 = __ldg(&emb4[(size_t)tk[l + 2] * 64 + q]);
        float4 v3 = __ldg(&emb4[(size_t)tk[l + 3] * 64 + q]);
        float4 v4 = __ldg(&emb4[(size_t)tk[l + 4] * 64 + q]);
        float4 v5 = __ldg(&emb4[(size_t)tk[l + 5] * 64 + q]);
        float4 v6 = __ldg(&emb4[(size_t)tk[l + 6] * 64 + q]);
        float4 v7 = __ldg(&emb4[(size_t)tk[l + 7] * 64 + q]);
        a0.x += (v0.x + v1.x) + (v2.x + v3.x);
        a0.y += (v0.y + v1.y) + (v2.y + v3.y);
        a0.z += (v0.z + v1.z) + (v2.z + v3.z);
        a0.w += (v0.w + v1.w) + (v2.w + v3.w);
        a1.x += (v4.x + v5.x) + (v6.x + v7.x);
        a1.y += (v4.y + v5.y) + (v6.y + v7.y);
        a1.z += (v4.z + v5.z) + (v6.z + v7.z);
        a1.w += (v4.w + v5.w) + (v6.w + v7.w);
    }
    for (; l < len; ++l) {
        float4 v = __ldg(&emb4[(size_t)tk[l] * 64 + q]);
        a0.x += v.x; a0.y += v.y; a0.z += v.z; a0.w += v.w;
    }
    const float inv = 1.f / (float)len;
    float4 o;
    o.x = (a0.x + a1.x) * inv;
    o.y = (a0.y + a1.y) * inv;
    o.z = (a0.z + a1.z) * inv;
    o.w = (a0.w + a1.w) * inv;
    ((float4*)g_pooled)[(size_t)(b0 + r) * 64 + q] = o;
}

// ============================================================
// Kernel 2: Z = pooled @ W1^T + b1, scalar 4x4 tiles, fused
// per-row-block column sum/sumsq stats in the epilogue.
// BM=BN=BK=64, 256 threads. grid (4, 64).
// ============================================================
__global__ void __launch_bounds__(256) gemm_kernel(
    const float* __restrict__ A,
    const float* __restrict__ W,
    const float* __restrict__ b1,
    float* __restrict__ Z)
{
    __shared__ __align__(16) float As[64][68];
    __shared__ __align__(16) float Bs[64][68];

    const int tid = threadIdx.x;
    const int bm = blockIdx.y * 64;
    const int bn = blockIdx.x * 64;
    const int tx = tid & 15;
    const int ty = tid >> 4;

    float c[4][4] = {};

    for (int k0 = 0; k0 < D_; k0 += 64) {
        #pragma unroll
        for (int j = 0; j < 4; ++j) {
            int idx = tid + j * 256;
            int m   = idx >> 4;            // 0..63
            int k4  = idx & 15;            // 0..15
            float4 va = *(const float4*)&A[(size_t)(bm + m) * D_ + k0 + k4 * 4];
            As[k4 * 4 + 0][m] = va.x; As[k4 * 4 + 1][m] = va.y;
            As[k4 * 4 + 2][m] = va.z; As[k4 * 4 + 3][m] = va.w;
            float4 vb = *(const float4*)&W[(size_t)(bn + m) * D_ + k0 + k4 * 4];
            Bs[k4 * 4 + 0][m] = vb.x; Bs[k4 * 4 + 1][m] = vb.y;
            Bs[k4 * 4 + 2][m] = vb.z; Bs[k4 * 4 + 3][m] = vb.w;
        }
        __syncthreads();

        #pragma unroll
        for (int kk = 0; kk < 64; ++kk) {
            float4 a  = *(const float4*)&As[kk][ty * 4];
            float4 bv = *(const float4*)&Bs[kk][tx * 4];
            float ar[4] = {a.x, a.y, a.z, a.w};
            float br[4] = {bv.x, bv.y, bv.z, bv.w};
            #pragma unroll
            for (int i = 0; i < 4; ++i)
                #pragma unroll
                for (int jj = 0; jj < 4; ++jj)
                    c[i][jj] = fmaf(ar[i], br[jj], c[i][jj]);
        }
        __syncthreads();
    }

    // bias + store Z + per-thread column sums/sumsq
    float s[4] = {0, 0, 0, 0}, ss[4] = {0, 0, 0, 0};
    #pragma unroll
    for (int jj = 0; jj < 4; ++jj) {
        float bias = b1[bn + tx * 4 + jj];
        #pragma unroll
        for (int i = 0; i < 4; ++i) {
            float z = c[i][jj] + bias;
            Z[(size_t)(bm + ty * 4 + i) * D_ + bn + tx * 4 + jj] = z;
            s[jj]  += z;
            ss[jj] = fmaf(z, z, ss[jj]);
        }
    }

    // block reduction over ty (16) into g_part — reuse As storage
    float* rs  = &As[0][0];       // [16][64] sums
    float* rss = rs + 16 * 64;    // [16][64] sumsq
    #pragma unroll
    for (int jj = 0; jj < 4; ++jj) {
        rs [ty * 64 + tx * 4 + jj] = s[jj];
        rss[ty * 64 + tx * 4 + jj] = ss[jj];
    }
    __syncthreads();
    #pragma unroll
    for (int st = 8; st >= 1; st >>= 1) {
        if (ty < st) {
            #pragma unroll
            for (int jj = 0; jj < 4; ++jj) {
                int cc = tx * 4 + jj;
                rs [ty * 64 + cc] += rs [(ty + st) * 64 + cc];
                rss[ty * 64 + cc] += rss[(ty + st) * 64 + cc];
            }
        }
        __syncthreads();
    }
    if (ty == 0) {
        #pragma unroll
        for (int jj = 0; jj < 4; ++jj) {
            int cc = tx * 4 + jj;
            g_part[blockIdx.y * D_ + bn + cc]            = rs [cc];
            g_part[64 * D_ + blockIdx.y * D_ + bn + cc]  = rss[cc];
        }
    }
}

// ============================================================
// Kernel 3: BN finalize + BN+ReLU+dot(w2)+BCE, with last-block
// loss reduction (monotonic ticket; deterministic fixed-order sum).
// grid 128 x 256 threads; block = 32 rows; warp = 4 rows.
// ============================================================
__global__ void __launch_bounds__(256) head_kernel(
    const float* __restrict__ Z,
    const float* __restrict__ gamma,
    const float* __restrict__ beta,
    const float* __restrict__ w2,
    const float* __restrict__ b2,
    const float* __restrict__ t,
    float* __restrict__ out)
{
    const int tid  = threadIdx.x;
    const int lane = tid & 31;
    const int warp = tid >> 5;

    __shared__ float s_g[D_], s_be[D_], s_w[D_];
    __shared__ float red[8];
    __shared__ int s_last;

    // Phase 1: finalize BN stats for dim d = tid (redundant per block)
    {
        float sm = 0.f, sq = 0.f;
        #pragma unroll 8
        for (int rb = 0; rb < 64; ++rb) {
            sm += g_part[rb * D_ + tid];
            sq += g_part[64 * D_ + rb * D_ + tid];
        }
        float mu   = sm * (1.f / (float)B_);
        float var  = sq * (1.f / (float)B_) - mu * mu;
        float rstd = rsqrtf(var + BN_EPS);
        float g    = gamma[tid] * rstd;
        s_g[tid]  = g;
        s_be[tid] = beta[tid] - g * mu;
        s_w[tid]  = w2[tid];
    }
    __syncthreads();

    // Phase 2: each warp processes 4 rows, 4 independent reduce chains
    const int row0 = blockIdx.x * 32 + warp * 4;
    const float b2v = b2[0];

    float acc[4] = {0.f, 0.f, 0.f, 0.f};
    #pragma unroll
    for (int k = 0; k < 8; ++k) {
        int dm = lane + 32 * k;
        float gk = s_g[dm], bek = s_be[dm], wk = s_w[dm];
        #pragma unroll
        for (int r = 0; r < 4; ++r) {
            float zv = Z[(size_t)(row0 + r) * D_ + dm];
            acc[r] += fmaxf(fmaf(gk, zv, bek), 0.f) * wk;
        }
    }
    #pragma unroll
    for (int off = 16; off > 0; off >>= 1) {
        #pragma unroll
        for (int r = 0; r < 4; ++r)
            acc[r] += __shfl_xor_sync(0xFFFFFFFFu, acc[r], off);
    }

    if (lane == 0) {
        float lossacc = 0.f;
        #pragma unroll
        for (int r = 0; r < 4; ++r) {
            float l = acc[r] + b2v;
            out[1 + row0 + r] = l;
            float tb = t[row0 + r];
            lossacc += fmaxf(l, 0.f) - l * tb + log1pf(expf(-fabsf(l)));
        }
        red[warp] = lossacc;
    }
    __syncthreads();

    // per-block loss partial + last-block election (monotonic ticket)
    if (tid == 0) {
        float sum = 0.f;
        #pragma unroll
        for (int w = 0; w < 8; ++w) sum += red[w];
        g_lossp[blockIdx.x] = sum;
        __threadfence();
        unsigned int my = atomicAdd(&g_ticket, 1u);
        s_last = ((my + 1u) & 127u) == 0u;   // last of this replay's 128
    }
    __syncthreads();

    // Phase 3: last block sums the 128 partials (fixed order, 1 warp)
    if (s_last) {
        __threadfence();
        if (warp == 0) {
            float v = g_lossp[lane] + g_lossp[lane + 32] +
                      g_lossp[lane + 64] + g_lossp[lane + 96];
            #pragma unroll
            for (int off = 16; off > 0; off >>= 1)
                v += __shfl_xor_sync(0xFFFFFFFFu, v, off);
            if (lane == 0) out[0] = v * (1.f / (float)B_);
        }
    }
}

// ============================================================
// launch: 3 kernels
// ============================================================
extern "C" void kernel_launch(void* const* d_in, const int* in_sizes, int n_in,
                              void* d_out, int out_size)
{
    const int*   tokens  = (const int*)d_in[0];
    const int*   lengths = (const int*)d_in[1];
    const float* t       = (const float*)d_in[2];
    const float* emb     = (const float*)d_in[3];
    const float* W1      = (const float*)d_in[4];
    const float* b1      = (const float*)d_in[5];
    const float* gamma   = (const float*)d_in[6];
    const float* beta    = (const float*)d_in[7];
    const float* w2      = (const float*)d_in[8];
    const float* b2      = (const float*)d_in[9];
    float* out = (float*)d_out;

    float* pooled; cudaGetSymbolAddress((void**)&pooled, g_pooled);
    float* z;      cudaGetSymbolAddress((void**)&z,      g_z);

    pool_kernel<<<B_ / 4, 256>>>(tokens, lengths, emb);

    dim3 ggrid(D_ / 64, B_ / 64);   // (4, 64)
    gemm_kernel<<<ggrid, 256>>>(pooled, W1, b1, z);

    head_kernel<<<B_ / 32, 256>>>(z, gamma, beta, w2, b2, t, out);
}

// round 5
// speedup vs baseline: 1.4635x; 1.1790x over previous
#include <cuda_runtime.h>
#include <cuda_bf16.h>
#include <math.h>

// Problem shapes (fixed by the dataset)
#define B_  4096
#define L_  200
#define D_  256
#define BN_EPS 1e-5f

// -------- scratch (no allocations allowed) --------
__device__ float g_pp[2 * B_ * D_];          // 8 MB: per-half partial sums
__device__ float g_z[B_ * D_];               // 4 MB
__device__ float g_part[2 * 64 * D_];        // per-bm-tile col sums / sumsq
__device__ float g_lossp[128];               // per-head-block loss partials
__device__ unsigned int g_ticket;            // monotonic last-block ticket

// ============================================================
// Kernel 1: ragged gather partial-pool.
// 1 block = (row, token-half). 8192 blocks x 64 threads.
// Thread q owns float4 dim-quad q; 8 LDG.128 in flight (unroll 8).
// Work per block <= 100 tokens -> fine-grained load balance.
// ============================================================
__global__ void __launch_bounds__(64) pool_kernel(
    const int* __restrict__ tokens,
    const int* __restrict__ lengths,
    const float* __restrict__ emb)
{
    const int bid  = blockIdx.x;
    const int row  = bid >> 1;
    const int half = bid & 1;
    const int tid  = threadIdx.x;
    __shared__ int s_tok[104];

    const int len   = lengths[row];
    const int n0    = len >> 1;
    const int start = half ? n0 : 0;
    const int cnt   = half ? (len - n0) : n0;

    for (int i = tid; i < cnt; i += 64)
        s_tok[i] = tokens[row * L_ + start + i];
    __syncthreads();

    const float4* __restrict__ emb4 = (const float4*)emb;  // row stride 64

    float4 a0 = make_float4(0.f, 0.f, 0.f, 0.f);
    float4 a1 = make_float4(0.f, 0.f, 0.f, 0.f);
    int l = 0;
    for (; l + 8 <= cnt; l += 8) {
        float4 v0 = __ldg(&emb4[(size_t)s_tok[l + 0] * 64 + tid]);
        float4 v1 = __ldg(&emb4[(size_t)s_tok[l + 1] * 64 + tid]);
        float4 v2 = __ldg(&emb4[(size_t)s_tok[l + 2] * 64 + tid]);
        float4 v3 = __ldg(&emb4[(size_t)s_tok[l + 3] * 64 + tid]);
        float4 v4 = __ldg(&emb4[(size_t)s_tok[l + 4] * 64 + tid]);
        float4 v5 = __ldg(&emb4[(size_t)s_tok[l + 5] * 64 + tid]);
        float4 v6 = __ldg(&emb4[(size_t)s_tok[l + 6] * 64 + tid]);
        float4 v7 = __ldg(&emb4[(size_t)s_tok[l + 7] * 64 + tid]);
        a0.x += (v0.x + v1.x) + (v2.x + v3.x);
        a0.y += (v0.y + v1.y) + (v2.y + v3.y);
        a0.z += (v0.z + v1.z) + (v2.z + v3.z);
        a0.w += (v0.w + v1.w) + (v2.w + v3.w);
        a1.x += (v4.x + v5.x) + (v6.x + v7.x);
        a1.y += (v4.y + v5.y) + (v6.y + v7.y);
        a1.z += (v4.z + v5.z) + (v6.z + v7.z);
        a1.w += (v4.w + v5.w) + (v6.w + v7.w);
    }
    for (; l < cnt; ++l) {
        float4 v = __ldg(&emb4[(size_t)s_tok[l] * 64 + tid]);
        a0.x += v.x; a0.y += v.y; a0.z += v.z; a0.w += v.w;
    }
    float4 o;
    o.x = a0.x + a1.x; o.y = a0.y + a1.y;
    o.z = a0.z + a1.z; o.w = a0.w + a1.w;
    ((float4*)g_pp)[((size_t)half * B_ + row) * 64 + tid] = o;
}

// ============================================================
// Kernel 2: Z = pooled @ W1^T + b1 where pooled is assembled on
// the fly from the two half-partials: (pp0+pp1) * (1/len).
// Scalar 4x4 tiles, BM=BN=BK=64, fused stats epilogue. grid (4,64).
// ============================================================
__global__ void __launch_bounds__(256) gemm_kernel(
    const int*   __restrict__ lengths,
    const float* __restrict__ W,
    const float* __restrict__ b1,
    float* __restrict__ Z)
{
    __shared__ __align__(16) float As[64][68];
    __shared__ __align__(16) float Bs[64][68];
    __shared__ float s_inv[64];

    const int tid = threadIdx.x;
    const int bm = blockIdx.y * 64;
    const int bn = blockIdx.x * 64;
    const int tx = tid & 15;
    const int ty = tid >> 4;

    if (tid < 64) s_inv[tid] = 1.f / (float)lengths[bm + tid];
    __syncthreads();

    const float4* __restrict__ pp4 = (const float4*)g_pp;

    float c[4][4] = {};

    for (int k0 = 0; k0 < D_; k0 += 64) {
        #pragma unroll
        for (int j = 0; j < 4; ++j) {
            int idx = tid + j * 256;
            int m   = idx >> 4;            // 0..63
            int k4  = idx & 15;            // 0..15
            int fi  = (k0 >> 2) + k4;      // float4 col index
            float4 p0 = pp4[(size_t)(bm + m) * 64 + fi];
            float4 p1 = pp4[((size_t)B_ + bm + m) * 64 + fi];
            float inv = s_inv[m];
            As[k4 * 4 + 0][m] = (p0.x + p1.x) * inv;
            As[k4 * 4 + 1][m] = (p0.y + p1.y) * inv;
            As[k4 * 4 + 2][m] = (p0.z + p1.z) * inv;
            As[k4 * 4 + 3][m] = (p0.w + p1.w) * inv;
            float4 vb = *(const float4*)&W[(size_t)(bn + m) * D_ + k0 + k4 * 4];
            Bs[k4 * 4 + 0][m] = vb.x; Bs[k4 * 4 + 1][m] = vb.y;
            Bs[k4 * 4 + 2][m] = vb.z; Bs[k4 * 4 + 3][m] = vb.w;
        }
        __syncthreads();

        #pragma unroll
        for (int kk = 0; kk < 64; ++kk) {
            float4 a  = *(const float4*)&As[kk][ty * 4];
            float4 bv = *(const float4*)&Bs[kk][tx * 4];
            float ar[4] = {a.x, a.y, a.z, a.w};
            float br[4] = {bv.x, bv.y, bv.z, bv.w};
            #pragma unroll
            for (int i = 0; i < 4; ++i)
                #pragma unroll
                for (int jj = 0; jj < 4; ++jj)
                    c[i][jj] = fmaf(ar[i], br[jj], c[i][jj]);
        }
        __syncthreads();
    }

    // bias + store Z + per-thread column sums/sumsq
    float s[4] = {0, 0, 0, 0}, ss[4] = {0, 0, 0, 0};
    #pragma unroll
    for (int jj = 0; jj < 4; ++jj) {
        float bias = b1[bn + tx * 4 + jj];
        #pragma unroll
        for (int i = 0; i < 4; ++i) {
            float z = c[i][jj] + bias;
            Z[(size_t)(bm + ty * 4 + i) * D_ + bn + tx * 4 + jj] = z;
            s[jj]  += z;
            ss[jj] = fmaf(z, z, ss[jj]);
        }
    }

    // block reduction over ty (16) into g_part — reuse As storage
    float* rs  = &As[0][0];       // [16][64] sums
    float* rss = rs + 16 * 64;    // [16][64] sumsq
    #pragma unroll
    for (int jj = 0; jj < 4; ++jj) {
        rs [ty * 64 + tx * 4 + jj] = s[jj];
        rss[ty * 64 + tx * 4 + jj] = ss[jj];
    }
    __syncthreads();
    #pragma unroll
    for (int st = 8; st >= 1; st >>= 1) {
        if (ty < st) {
            #pragma unroll
            for (int jj = 0; jj < 4; ++jj) {
                int cc = tx * 4 + jj;
                rs [ty * 64 + cc] += rs [(ty + st) * 64 + cc];
                rss[ty * 64 + cc] += rss[(ty + st) * 64 + cc];
            }
        }
        __syncthreads();
    }
    if (ty == 0) {
        #pragma unroll
        for (int jj = 0; jj < 4; ++jj) {
            int cc = tx * 4 + jj;
            g_part[blockIdx.y * D_ + bn + cc]            = rs [cc];
            g_part[64 * D_ + blockIdx.y * D_ + bn + cc]  = rss[cc];
        }
    }
}

// ============================================================
// Kernel 3: BN finalize + BN+ReLU+dot(w2)+BCE, with last-block
// loss reduction (monotonic ticket; deterministic fixed-order sum).
// grid 128 x 256 threads; block = 32 rows; warp = 4 rows.
// ============================================================
__global__ void __launch_bounds__(256) head_kernel(
    const float* __restrict__ Z,
    const float* __restrict__ gamma,
    const float* __restrict__ beta,
    const float* __restrict__ w2,
    const float* __restrict__ b2,
    const float* __restrict__ t,
    float* __restrict__ out)
{
    const int tid  = threadIdx.x;
    const int lane = tid & 31;
    const int warp = tid >> 5;

    __shared__ float s_g[D_], s_be[D_], s_w[D_];
    __shared__ float red[8];
    __shared__ int s_last;

    // Phase 1: finalize BN stats for dim d = tid (redundant per block)
    {
        float sm = 0.f, sq = 0.f;
        #pragma unroll 8
        for (int rb = 0; rb < 64; ++rb) {
            sm += g_part[rb * D_ + tid];
            sq += g_part[64 * D_ + rb * D_ + tid];
        }
        float mu   = sm * (1.f / (float)B_);
        float var  = sq * (1.f / (float)B_) - mu * mu;
        float rstd = rsqrtf(var + BN_EPS);
        float g    = gamma[tid] * rstd;
        s_g[tid]  = g;
        s_be[tid] = beta[tid] - g * mu;
        s_w[tid]  = w2[tid];
    }
    __syncthreads();

    // Phase 2: each warp processes 4 rows, 4 independent reduce chains
    const int row0 = blockIdx.x * 32 + warp * 4;
    const float b2v = b2[0];

    float acc[4] = {0.f, 0.f, 0.f, 0.f};
    #pragma unroll
    for (int k = 0; k < 8; ++k) {
        int dm = lane + 32 * k;
        float gk = s_g[dm], bek = s_be[dm], wk = s_w[dm];
        #pragma unroll
        for (int r = 0; r < 4; ++r) {
            float zv = Z[(size_t)(row0 + r) * D_ + dm];
            acc[r] += fmaxf(fmaf(gk, zv, bek), 0.f) * wk;
        }
    }
    #pragma unroll
    for (int off = 16; off > 0; off >>= 1) {
        #pragma unroll
        for (int r = 0; r < 4; ++r)
            acc[r] += __shfl_xor_sync(0xFFFFFFFFu, acc[r], off);
    }

    if (lane == 0) {
        float lossacc = 0.f;
        #pragma unroll
        for (int r = 0; r < 4; ++r) {
            float l = acc[r] + b2v;
            out[1 + row0 + r] = l;
            float tb = t[row0 + r];
            lossacc += fmaxf(l, 0.f) - l * tb + log1pf(expf(-fabsf(l)));
        }
        red[warp] = lossacc;
    }
    __syncthreads();

    // per-block loss partial + last-block election (monotonic ticket)
    if (tid == 0) {
        float sum = 0.f;
        #pragma unroll
        for (int w = 0; w < 8; ++w) sum += red[w];
        g_lossp[blockIdx.x] = sum;
        __threadfence();
        unsigned int my = atomicAdd(&g_ticket, 1u);
        s_last = ((my + 1u) & 127u) == 0u;   // last of this replay's 128
    }
    __syncthreads();

    // Phase 3: last block sums the 128 partials (fixed order, 1 warp)
    if (s_last) {
        __threadfence();
        if (warp == 0) {
            float v = g_lossp[lane] + g_lossp[lane + 32] +
                      g_lossp[lane + 64] + g_lossp[lane + 96];
            #pragma unroll
            for (int off = 16; off > 0; off >>= 1)
                v += __shfl_xor_sync(0xFFFFFFFFu, v, off);
            if (lane == 0) out[0] = v * (1.f / (float)B_);
        }
    }
}

// ============================================================
// launch: 3 kernels
// ============================================================
extern "C" void kernel_launch(void* const* d_in, const int* in_sizes, int n_in,
                              void* d_out, int out_size)
{
    const int*   tokens  = (const int*)d_in[0];
    const int*   lengths = (const int*)d_in[1];
    const float* t       = (const float*)d_in[2];
    const float* emb     = (const float*)d_in[3];
    const float* W1      = (const float*)d_in[4];
    const float* b1      = (const float*)d_in[5];
    const float* gamma   = (const float*)d_in[6];
    const float* beta    = (const float*)d_in[7];
    const float* w2      = (const float*)d_in[8];
    const float* b2      = (const float*)d_in[9];
    float* out = (float*)d_out;

    float* z; cudaGetSymbolAddress((void**)&z, g_z);

    pool_kernel<<<B_ * 2, 64>>>(tokens, lengths, emb);

    dim3 ggrid(D_ / 64, B_ / 64);   // (4, 64)
    gemm_kernel<<<ggrid, 256>>>(lengths, W1, b1, z);

    head_kernel<<<B_ / 32, 256>>>(z, gamma, beta, w2, b2, t, out);
}

// round 7
// speedup vs baseline: 1.7304x; 1.1823x over previous
#include <cuda_runtime.h>
#include <cuda_bf16.h>
#include <math.h>

// Problem shapes (fixed by the dataset)
#define B_  4096
#define L_  200
#define D_  256
#define BN_EPS 1e-5f

// -------- scratch (no allocations allowed) --------
__device__ float g_pp[2 * B_ * D_];          // 8 MB: per-half partial sums
__device__ float g_z[B_ * D_];               // 4 MB
__device__ float g_part[2 * 64 * D_];        // per-bm-tile col sums / sumsq
__device__ float g_lossp[128];               // per-head-block loss partials
__device__ unsigned int g_ticket;            // head: monotonic last-block ticket

// float -> tf32 (round to nearest, bit pattern in u32)
__device__ __forceinline__ unsigned int f2tf32(float f)
{
    unsigned int u;
    asm("cvt.rna.tf32.f32 %0, %1;" : "=r"(u) : "f"(f));
    return u;
}

// ============================================================
// Kernel 1: ragged gather partial-pool (unchanged from R5 best).
// 1 block = (row, token-half). 8192 blocks x 64 threads.
// ============================================================
__global__ void __launch_bounds__(64) pool_kernel(
    const int* __restrict__ tokens,
    const int* __restrict__ lengths,
    const float* __restrict__ emb)
{
    const int bid  = blockIdx.x;
    const int row  = bid >> 1;
    const int half = bid & 1;
    const int tid  = threadIdx.x;
    __shared__ int s_tok[104];

    const int len   = lengths[row];
    const int n0    = len >> 1;
    const int start = half ? n0 : 0;
    const int cnt   = half ? (len - n0) : n0;

    for (int i = tid; i < cnt; i += 64)
        s_tok[i] = tokens[row * L_ + start + i];
    __syncthreads();

    const float4* __restrict__ emb4 = (const float4*)emb;  // row stride 64

    float4 a0 = make_float4(0.f, 0.f, 0.f, 0.f);
    float4 a1 = make_float4(0.f, 0.f, 0.f, 0.f);
    int l = 0;
    for (; l + 8 <= cnt; l += 8) {
        float4 v0 = __ldg(&emb4[(size_t)s_tok[l + 0] * 64 + tid]);
        float4 v1 = __ldg(&emb4[(size_t)s_tok[l + 1] * 64 + tid]);
        float4 v2 = __ldg(&emb4[(size_t)s_tok[l + 2] * 64 + tid]);
        float4 v3 = __ldg(&emb4[(size_t)s_tok[l + 3] * 64 + tid]);
        float4 v4 = __ldg(&emb4[(size_t)s_tok[l + 4] * 64 + tid]);
        float4 v5 = __ldg(&emb4[(size_t)s_tok[l + 5] * 64 + tid]);
        float4 v6 = __ldg(&emb4[(size_t)s_tok[l + 6] * 64 + tid]);
        float4 v7 = __ldg(&emb4[(size_t)s_tok[l + 7] * 64 + tid]);
        a0.x += (v0.x + v1.x) + (v2.x + v3.x);
        a0.y += (v0.y + v1.y) + (v2.y + v3.y);
        a0.z += (v0.z + v1.z) + (v2.z + v3.z);
        a0.w += (v0.w + v1.w) + (v2.w + v3.w);
        a1.x += (v4.x + v5.x) + (v6.x + v7.x);
        a1.y += (v4.y + v5.y) + (v6.y + v7.y);
        a1.z += (v4.z + v5.z) + (v6.z + v7.z);
        a1.w += (v4.w + v5.w) + (v6.w + v7.w);
    }
    for (; l < cnt; ++l) {
        float4 v = __ldg(&emb4[(size_t)s_tok[l] * 64 + tid]);
        a0.x += v.x; a0.y += v.y; a0.z += v.z; a0.w += v.w;
    }
    float4 o;
    o.x = a0.x + a1.x; o.y = a0.y + a1.y;
    o.z = a0.z + a1.z; o.w = a0.w + a1.w;
    ((float4*)g_pp)[((size_t)half * B_ + row) * 64 + tid] = o;
}

// ============================================================
// Kernel 2: Z = pooled @ W1^T + b1 via tf32 mma.sync (m16n8k8),
// pooled assembled on the fly from the two half-partials.
// BM=BN=64, K chunked by 64. 256 threads = 8 warps:
//   wm = warp>>1 (m16 slice), wn = warp&1 (n32 slice, 4 x n8).
// Fused per-row-block column sum/sumsq epilogue. grid (4,64).
// ============================================================
__global__ void __launch_bounds__(256) gemm_kernel(
    const int*   __restrict__ lengths,
    const float* __restrict__ W,
    const float* __restrict__ b1,
    float* __restrict__ Z)
{
    __shared__ __align__(16) unsigned int As_u[64][68];  // tf32 A [m][k]
    __shared__ __align__(16) unsigned int Bs_u[64][68];  // tf32 W [n][k]
    __shared__ float s_inv[64];

    const int tid  = threadIdx.x;
    const int lane = tid & 31;
    const int warp = tid >> 5;
    const int g    = lane >> 2;          // group id (0..7)
    const int t    = lane & 3;           // thread in group (0..3)
    const int wm   = warp >> 1;          // 0..3 -> m offset 16*wm
    const int wn   = warp & 1;           // 0..1 -> n offset 32*wn
    const int bm   = blockIdx.y * 64;
    const int bn   = blockIdx.x * 64;

    if (tid < 64) s_inv[tid] = 1.f / (float)lengths[bm + tid];
    __syncthreads();

    const float4* __restrict__ pp4 = (const float4*)g_pp;

    float c[4][4] = {};   // c[nb][0..3]: rows {g,g,g+8,g+8}, cols {2t,2t+1}

    for (int k0 = 0; k0 < D_; k0 += 64) {
        #pragma unroll
        for (int j = 0; j < 4; ++j) {
            int idx = tid + j * 256;
            int m   = idx >> 4;            // 0..63
            int k4  = idx & 15;            // 0..15
            int fi  = (k0 >> 2) + k4;      // float4 col index in [0,64)
            float4 p0 = pp4[(size_t)(bm + m) * 64 + fi];
            float4 p1 = pp4[((size_t)B_ + bm + m) * 64 + fi];
            float inv = s_inv[m];
            uint4 ua;
            ua.x = f2tf32((p0.x + p1.x) * inv);
            ua.y = f2tf32((p0.y + p1.y) * inv);
            ua.z = f2tf32((p0.z + p1.z) * inv);
            ua.w = f2tf32((p0.w + p1.w) * inv);
            *(uint4*)&As_u[m][k4 * 4] = ua;
            float4 vb = *(const float4*)&W[(size_t)(bn + m) * D_ + k0 + k4 * 4];
            uint4 ub;
            ub.x = f2tf32(vb.x); ub.y = f2tf32(vb.y);
            ub.z = f2tf32(vb.z); ub.w = f2tf32(vb.w);
            *(uint4*)&Bs_u[m][k4 * 4] = ub;
        }
        __syncthreads();

        const int am = wm * 16 + g;
        #pragma unroll
        for (int ks = 0; ks < 8; ++ks) {
            const int kc = ks * 8;
            unsigned int a0 = As_u[am    ][kc + t];
            unsigned int a1 = As_u[am + 8][kc + t];
            unsigned int a2 = As_u[am    ][kc + t + 4];
            unsigned int a3 = As_u[am + 8][kc + t + 4];
            #pragma unroll
            for (int nb = 0; nb < 4; ++nb) {
                const int bnrow = wn * 32 + nb * 8 + g;
                unsigned int b0 = Bs_u[bnrow][kc + t];
                unsigned int b1r = Bs_u[bnrow][kc + t + 4];
                asm volatile(
                    "mma.sync.aligned.m16n8k8.row.col.f32.tf32.tf32.f32 "
                    "{%0,%1,%2,%3}, {%4,%5,%6,%7}, {%8,%9}, {%0,%1,%2,%3};"
                    : "+f"(c[nb][0]), "+f"(c[nb][1]),
                      "+f"(c[nb][2]), "+f"(c[nb][3])
                    : "r"(a0), "r"(a1), "r"(a2), "r"(a3),
                      "r"(b0), "r"(b1r));
            }
        }
        __syncthreads();
    }

    // ---------------- epilogue: bias + Z store + fused stats -------------
    const int row0 = bm + wm * 16 + g;       // and row0+8
    float colsum[8], colsq[8];               // 4 nb x 2 cols

    #pragma unroll
    for (int nb = 0; nb < 4; ++nb) {
        const int col = bn + wn * 32 + nb * 8 + 2 * t;
        const float bz0 = b1[col], bz1 = b1[col + 1];
        float v00 = c[nb][0] + bz0, v01 = c[nb][1] + bz1;   // row0
        float v10 = c[nb][2] + bz0, v11 = c[nb][3] + bz1;   // row0+8
        *(float2*)&Z[(size_t)row0 * D_ + col]       = make_float2(v00, v01);
        *(float2*)&Z[(size_t)(row0 + 8) * D_ + col] = make_float2(v10, v11);
        colsum[nb * 2 + 0] = v00 + v10;
        colsum[nb * 2 + 1] = v01 + v11;
        colsq [nb * 2 + 0] = fmaf(v00, v00, v10 * v10);
        colsq [nb * 2 + 1] = fmaf(v01, v01, v11 * v11);
    }

    // stats reduction: 32 contributors (wm*8+g) per column, stride 65
    float* rs  = (float*)As_u;       // [32][65]
    float* rss = (float*)Bs_u;       // [32][65]
    const int contrib = wm * 8 + g;
    #pragma unroll
    for (int nb = 0; nb < 4; ++nb) {
        #pragma unroll
        for (int j = 0; j < 2; ++j) {
            int col = wn * 32 + nb * 8 + 2 * t + j;
            rs [contrib * 65 + col] = colsum[nb * 2 + j];
            rss[contrib * 65 + col] = colsq [nb * 2 + j];
        }
    }
    __syncthreads();
    if (tid < 64) {
        float s = 0.f, ss = 0.f;
        #pragma unroll 8
        for (int i = 0; i < 32; ++i) {
            s  += rs [i * 65 + tid];
            ss += rss[i * 65 + tid];
        }
        g_part[blockIdx.y * D_ + bn + tid]           = s;
        g_part[64 * D_ + blockIdx.y * D_ + bn + tid] = ss;
    }
}

// ============================================================
// Kernel 3: BN finalize + BN+ReLU+dot(w2)+BCE, with last-block
// loss reduction (monotonic ticket; deterministic fixed-order sum).
// grid 128 x 256 threads; block = 32 rows; warp = 4 rows.
// ============================================================
__global__ void __launch_bounds__(256) head_kernel(
    const float* __restrict__ Z,
    const float* __restrict__ gamma,
    const float* __restrict__ beta,
    const float* __restrict__ w2,
    const float* __restrict__ b2,
    const float* __restrict__ t,
    float* __restrict__ out)
{
    const int tid  = threadIdx.x;
    const int lane = tid & 31;
    const int warp = tid >> 5;

    __shared__ float s_g[D_], s_be[D_], s_w[D_];
    __shared__ float red[8];
    __shared__ int s_last;

    // Phase 1: finalize BN stats for dim d = tid (redundant per block)
    {
        float sm = 0.f, sq = 0.f;
        #pragma unroll 8
        for (int rb = 0; rb < 64; ++rb) {
            sm += g_part[rb * D_ + tid];
            sq += g_part[64 * D_ + rb * D_ + tid];
        }
        float mu   = sm * (1.f / (float)B_);
        float var  = sq * (1.f / (float)B_) - mu * mu;
        float rstd = rsqrtf(var + BN_EPS);
        float g    = gamma[tid] * rstd;
        s_g[tid]  = g;
        s_be[tid] = beta[tid] - g * mu;
        s_w[tid]  = w2[tid];
    }
    __syncthreads();

    // Phase 2: each warp processes 4 rows, 4 independent reduce chains
    const int row0 = blockIdx.x * 32 + warp * 4;
    const float b2v = b2[0];

    float acc[4] = {0.f, 0.f, 0.f, 0.f};
    #pragma unroll
    for (int k = 0; k < 8; ++k) {
        int dm = lane + 32 * k;
        float gk = s_g[dm], bek = s_be[dm], wk = s_w[dm];
        #pragma unroll
        for (int r = 0; r < 4; ++r) {
            float zv = Z[(size_t)(row0 + r) * D_ + dm];
            acc[r] += fmaxf(fmaf(gk, zv, bek), 0.f) * wk;
        }
    }
    #pragma unroll
    for (int off = 16; off > 0; off >>= 1) {
        #pragma unroll
        for (int r = 0; r < 4; ++r)
            acc[r] += __shfl_xor_sync(0xFFFFFFFFu, acc[r], off);
    }

    if (lane == 0) {
        float lossacc = 0.f;
        #pragma unroll
        for (int r = 0; r < 4; ++r) {
            float l = acc[r] + b2v;
            out[1 + row0 + r] = l;
            float tb = t[row0 + r];
            lossacc += fmaxf(l, 0.f) - l * tb + log1pf(expf(-fabsf(l)));
        }
        red[warp] = lossacc;
    }
    __syncthreads();

    // per-block loss partial + last-block election (monotonic ticket)
    if (tid == 0) {
        float sum = 0.f;
        #pragma unroll
        for (int w = 0; w < 8; ++w) sum += red[w];
        g_lossp[blockIdx.x] = sum;
        __threadfence();
        unsigned int my = atomicAdd(&g_ticket, 1u);
        s_last = ((my + 1u) & 127u) == 0u;   // last of this replay's 128
    }
    __syncthreads();

    // Phase 3: last block sums the 128 partials (fixed order, 1 warp)
    if (s_last) {
        __threadfence();
        if (warp == 0) {
            float v = g_lossp[lane] + g_lossp[lane + 32] +
                      g_lossp[lane + 64] + g_lossp[lane + 96];
            #pragma unroll
            for (int off = 16; off > 0; off >>= 1)
                v += __shfl_xor_sync(0xFFFFFFFFu, v, off);
            if (lane == 0) out[0] = v * (1.f / (float)B_);
        }
    }
}

// ============================================================
// launch: 3 kernels, serial (default stream)
// ============================================================
extern "C" void kernel_launch(void* const* d_in, const int* in_sizes, int n_in,
                              void* d_out, int out_size)
{
    const int*   tokens  = (const int*)d_in[0];
    const int*   lengths = (const int*)d_in[1];
    const float* t       = (const float*)d_in[2];
    const float* emb     = (const float*)d_in[3];
    const float* W1      = (const float*)d_in[4];
    const float* b1      = (const float*)d_in[5];
    const float* gamma   = (const float*)d_in[6];
    const float* beta    = (const float*)d_in[7];
    const float* w2      = (const float*)d_in[8];
    const float* b2      = (const float*)d_in[9];
    float* out = (float*)d_out;

    float* z; cudaGetSymbolAddress((void**)&z, g_z);

    pool_kernel<<<B_ * 2, 64>>>(tokens, lengths, emb);

    dim3 ggrid(D_ / 64, B_ / 64);   // (4, 64)
    gemm_kernel<<<ggrid, 256>>>(lengths, W1, b1, z);

    head_kernel<<<B_ / 32, 256>>>(z, gamma, beta, w2, b2, t, out);
}

// round 8
// speedup vs baseline: 1.9034x; 1.1000x over previous
#include <cuda_runtime.h>
#include <cuda_bf16.h>
#include <math.h>

// Problem shapes (fixed by the dataset)
#define B_  4096
#define L_  200
#define D_  256
#define BN_EPS 1e-5f

// -------- scratch (no allocations allowed) --------
__device__ float g_pp[2 * B_ * D_];          // 8 MB: per-half partial sums
__device__ float g_z[B_ * D_];               // 4 MB
__device__ float g_part[2 * 64 * D_];        // per-bm-tile col sums / sumsq
__device__ float g_lossp[256];               // per-block loss partials
__device__ unsigned int g_ticket;            // monotonic last-block ticket
__device__ unsigned int g_syncc[2];          // monotonic grid-sync counters

// float -> tf32 (round to nearest, bit pattern in u32)
__device__ __forceinline__ unsigned int f2tf32(float f)
{
    unsigned int u;
    asm("cvt.rna.tf32.f32 %0, %1;" : "=r"(u) : "f"(f));
    return u;
}

// emb load: non-coherent, L2 evict_last policy (keep table resident)
__device__ __forceinline__ float4 ldg_keep(const float4* p, unsigned long long pol)
{
    float4 v;
    asm volatile("ld.global.nc.L2::cache_hint.v4.f32 {%0,%1,%2,%3}, [%4], %5;"
                 : "=f"(v.x), "=f"(v.y), "=f"(v.z), "=f"(v.w)
                 : "l"(p), "l"(pol));
    return v;
}

// ============================================================
// Kernel 1: ragged gather partial-pool.
// 1 block = (row, token-half). 8192 blocks x 64 threads.
// emb loads pinned to L2 (evict_last); scratch streamed (cs).
// ============================================================
__global__ void __launch_bounds__(64) pool_kernel(
    const int* __restrict__ tokens,
    const int* __restrict__ lengths,
    const float* __restrict__ emb)
{
    const int bid  = blockIdx.x;
    const int row  = bid >> 1;
    const int half = bid & 1;
    const int tid  = threadIdx.x;
    __shared__ int s_tok[104];

    unsigned long long pol;
    asm("createpolicy.fractional.L2::evict_last.b64 %0, 1.0;" : "=l"(pol));

    const int len   = lengths[row];
    const int n0    = len >> 1;
    const int start = half ? n0 : 0;
    const int cnt   = half ? (len - n0) : n0;

    for (int i = tid; i < cnt; i += 64)
        s_tok[i] = __ldcs(&tokens[row * L_ + start + i]);
    __syncthreads();

    const float4* __restrict__ emb4 = (const float4*)emb;  // row stride 64

    float4 a0 = make_float4(0.f, 0.f, 0.f, 0.f);
    float4 a1 = make_float4(0.f, 0.f, 0.f, 0.f);
    int l = 0;
    for (; l + 8 <= cnt; l += 8) {
        float4 v0 = ldg_keep(&emb4[(size_t)s_tok[l + 0] * 64 + tid], pol);
        float4 v1 = ldg_keep(&emb4[(size_t)s_tok[l + 1] * 64 + tid], pol);
        float4 v2 = ldg_keep(&emb4[(size_t)s_tok[l + 2] * 64 + tid], pol);
        float4 v3 = ldg_keep(&emb4[(size_t)s_tok[l + 3] * 64 + tid], pol);
        float4 v4 = ldg_keep(&emb4[(size_t)s_tok[l + 4] * 64 + tid], pol);
        float4 v5 = ldg_keep(&emb4[(size_t)s_tok[l + 5] * 64 + tid], pol);
        float4 v6 = ldg_keep(&emb4[(size_t)s_tok[l + 6] * 64 + tid], pol);
        float4 v7 = ldg_keep(&emb4[(size_t)s_tok[l + 7] * 64 + tid], pol);
        a0.x += (v0.x + v1.x) + (v2.x + v3.x);
        a0.y += (v0.y + v1.y) + (v2.y + v3.y);
        a0.z += (v0.z + v1.z) + (v2.z + v3.z);
        a0.w += (v0.w + v1.w) + (v2.w + v3.w);
        a1.x += (v4.x + v5.x) + (v6.x + v7.x);
        a1.y += (v4.y + v5.y) + (v6.y + v7.y);
        a1.z += (v4.z + v5.z) + (v6.z + v7.z);
        a1.w += (v4.w + v5.w) + (v6.w + v7.w);
    }
    for (; l < cnt; ++l) {
        float4 v = ldg_keep(&emb4[(size_t)s_tok[l] * 64 + tid], pol);
        a0.x += v.x; a0.y += v.y; a0.z += v.z; a0.w += v.w;
    }
    float4 o;
    o.x = a0.x + a1.x; o.y = a0.y + a1.y;
    o.z = a0.z + a1.z; o.w = a0.w + a1.w;
    __stcs(&((float4*)g_pp)[((size_t)half * B_ + row) * 64 + tid], o);
}

// ------------------------------------------------------------
// Monotonic grid barrier (works across graph replays, no reset).
// Requires all NB blocks co-resident — guaranteed by launch_bounds(256,2).
// ------------------------------------------------------------
#define NB 256
__device__ __forceinline__ void gsync(int idx)
{
    __syncthreads();
    __threadfence();
    if (threadIdx.x == 0) {
        unsigned int my     = atomicAdd(&g_syncc[idx], 1u);
        unsigned int target = (my / NB + 1u) * NB;
        while (atomicAdd(&g_syncc[idx], 0u) < target)
            __nanosleep(64);
        __threadfence();
    }
    __syncthreads();
}

// ============================================================
// Kernel 2 (fused): tf32 GEMM + stats  ->  grid sync  ->
// BN finalize + BN+ReLU+dot(w2)+BCE + ticketed loss reduction.
// grid 256 x 256 threads, 2 blocks/SM guaranteed.
// GEMM: bm=(bid>>2)*64, bn=(bid&3)*64. Head: rows [bid*16, bid*16+16).
// ============================================================
__global__ void __launch_bounds__(256, 2) gemm_head_kernel(
    const int*   __restrict__ lengths,
    const float* __restrict__ W,
    const float* __restrict__ b1,
    const float* __restrict__ gamma,
    const float* __restrict__ beta,
    const float* __restrict__ w2,
    const float* __restrict__ b2,
    const float* __restrict__ t,
    float* __restrict__ Z,
    float* __restrict__ out)
{
    __shared__ union {
        struct {
            unsigned int As_u[64][68];
            unsigned int Bs_u[64][68];
            float s_inv[64];
        } g;
        struct {
            float s_g[D_], s_be[D_], s_w[D_];
            float red[8];
        } h;
    } sm;

    const int tid  = threadIdx.x;
    const int lane = tid & 31;
    const int warp = tid >> 5;
    const int bid  = blockIdx.x;

    // =================== Phase A: tf32 GEMM + stats ======================
    {
        const int g  = lane >> 2;
        const int tq = lane & 3;
        const int wm = warp >> 1;
        const int wn = warp & 1;
        const int bm = (bid >> 2) * 64;
        const int bn = (bid & 3) * 64;

        if (tid < 64) sm.g.s_inv[tid] = 1.f / (float)lengths[bm + tid];
        __syncthreads();

        const float4* __restrict__ pp4 = (const float4*)g_pp;

        float c[4][4] = {};

        for (int k0 = 0; k0 < D_; k0 += 64) {
            #pragma unroll
            for (int j = 0; j < 4; ++j) {
                int idx = tid + j * 256;
                int m   = idx >> 4;
                int k4  = idx & 15;
                int fi  = (k0 >> 2) + k4;
                float4 p0 = __ldcs(&pp4[(size_t)(bm + m) * 64 + fi]);
                float4 p1 = __ldcs(&pp4[((size_t)B_ + bm + m) * 64 + fi]);
                float inv = sm.g.s_inv[m];
                uint4 ua;
                ua.x = f2tf32((p0.x + p1.x) * inv);
                ua.y = f2tf32((p0.y + p1.y) * inv);
                ua.z = f2tf32((p0.z + p1.z) * inv);
                ua.w = f2tf32((p0.w + p1.w) * inv);
                *(uint4*)&sm.g.As_u[m][k4 * 4] = ua;
                float4 vb = *(const float4*)&W[(size_t)(bn + m) * D_ + k0 + k4 * 4];
                uint4 ub;
                ub.x = f2tf32(vb.x); ub.y = f2tf32(vb.y);
                ub.z = f2tf32(vb.z); ub.w = f2tf32(vb.w);
                *(uint4*)&sm.g.Bs_u[m][k4 * 4] = ub;
            }
            __syncthreads();

            const int am = wm * 16 + g;
            #pragma unroll
            for (int ks = 0; ks < 8; ++ks) {
                const int kc = ks * 8;
                unsigned int a0 = sm.g.As_u[am    ][kc + tq];
                unsigned int a1 = sm.g.As_u[am + 8][kc + tq];
                unsigned int a2 = sm.g.As_u[am    ][kc + tq + 4];
                unsigned int a3 = sm.g.As_u[am + 8][kc + tq + 4];
                #pragma unroll
                for (int nb = 0; nb < 4; ++nb) {
                    const int bnrow = wn * 32 + nb * 8 + g;
                    unsigned int b0  = sm.g.Bs_u[bnrow][kc + tq];
                    unsigned int b1r = sm.g.Bs_u[bnrow][kc + tq + 4];
                    asm volatile(
                        "mma.sync.aligned.m16n8k8.row.col.f32.tf32.tf32.f32 "
                        "{%0,%1,%2,%3}, {%4,%5,%6,%7}, {%8,%9}, {%0,%1,%2,%3};"
                        : "+f"(c[nb][0]), "+f"(c[nb][1]),
                          "+f"(c[nb][2]), "+f"(c[nb][3])
                        : "r"(a0), "r"(a1), "r"(a2), "r"(a3),
                          "r"(b0), "r"(b1r));
                }
            }
            __syncthreads();
        }

        // epilogue: bias + Z store + fused stats
        const int row0 = bm + wm * 16 + g;
        float colsum[8], colsq[8];

        #pragma unroll
        for (int nb = 0; nb < 4; ++nb) {
            const int col = bn + wn * 32 + nb * 8 + 2 * tq;
            const float bz0 = b1[col], bz1 = b1[col + 1];
            float v00 = c[nb][0] + bz0, v01 = c[nb][1] + bz1;
            float v10 = c[nb][2] + bz0, v11 = c[nb][3] + bz1;
            *(float2*)&Z[(size_t)row0 * D_ + col]       = make_float2(v00, v01);
            *(float2*)&Z[(size_t)(row0 + 8) * D_ + col] = make_float2(v10, v11);
            colsum[nb * 2 + 0] = v00 + v10;
            colsum[nb * 2 + 1] = v01 + v11;
            colsq [nb * 2 + 0] = fmaf(v00, v00, v10 * v10);
            colsq [nb * 2 + 1] = fmaf(v01, v01, v11 * v11);
        }

        float* rs  = (float*)sm.g.As_u;   // [32][65]
        float* rss = (float*)sm.g.Bs_u;   // [32][65]
        const int contrib = wm * 8 + g;
        #pragma unroll
        for (int nb = 0; nb < 4; ++nb) {
            #pragma unroll
            for (int j = 0; j < 2; ++j) {
                int col = wn * 32 + nb * 8 + 2 * tq + j;
                rs [contrib * 65 + col] = colsum[nb * 2 + j];
                rss[contrib * 65 + col] = colsq [nb * 2 + j];
            }
        }
        __syncthreads();
        if (tid < 64) {
            float s = 0.f, ssq = 0.f;
            #pragma unroll 8
            for (int i = 0; i < 32; ++i) {
                s   += rs [i * 65 + tid];
                ssq += rss[i * 65 + tid];
            }
            g_part[(bid >> 2) * D_ + bn + tid]           = s;
            g_part[64 * D_ + (bid >> 2) * D_ + bn + tid] = ssq;
        }
    }

    gsync(0);

    // =================== Phase B: head (16 rows/block) ===================
    {
        // fold stats for dim d = tid (redundant per block; L2-served)
        float smv = 0.f, sq = 0.f;
        #pragma unroll 8
        for (int rb = 0; rb < 64; ++rb) {
            smv += g_part[rb * D_ + tid];
            sq  += g_part[64 * D_ + rb * D_ + tid];
        }
        float mu   = smv * (1.f / (float)B_);
        float var  = sq  * (1.f / (float)B_) - mu * mu;
        float rstd = rsqrtf(var + BN_EPS);
        float gg   = gamma[tid] * rstd;
        sm.h.s_g[tid]  = gg;
        sm.h.s_be[tid] = beta[tid] - gg * mu;
        sm.h.s_w[tid]  = w2[tid];
        __syncthreads();

        const int row0 = bid * 16 + warp * 2;   // 2 rows per warp
        const float b2v = b2[0];

        float acc[2] = {0.f, 0.f};
        #pragma unroll
        for (int k = 0; k < 8; ++k) {
            int dm = lane + 32 * k;
            float gk = sm.h.s_g[dm], bek = sm.h.s_be[dm], wk = sm.h.s_w[dm];
            #pragma unroll
            for (int r = 0; r < 2; ++r) {
                float zv = Z[(size_t)(row0 + r) * D_ + dm];
                acc[r] += fmaxf(fmaf(gk, zv, bek), 0.f) * wk;
            }
        }
        #pragma unroll
        for (int off = 16; off > 0; off >>= 1) {
            acc[0] += __shfl_xor_sync(0xFFFFFFFFu, acc[0], off);
            acc[1] += __shfl_xor_sync(0xFFFFFFFFu, acc[1], off);
        }

        if (lane == 0) {
            float lossacc = 0.f;
            #pragma unroll
            for (int r = 0; r < 2; ++r) {
                float l = acc[r] + b2v;
                out[1 + row0 + r] = l;
                float tb = t[row0 + r];
                lossacc += fmaxf(l, 0.f) - l * tb + log1pf(expf(-fabsf(l)));
            }
            sm.h.red[warp] = lossacc;
        }
        __syncthreads();

        __shared__ int s_last;
        if (tid == 0) {
            float sum = 0.f;
            #pragma unroll
            for (int w = 0; w < 8; ++w) sum += sm.h.red[w];
            g_lossp[bid] = sum;
            __threadfence();
            unsigned int my = atomicAdd(&g_ticket, 1u);
            s_last = ((my + 1u) & 255u) == 0u;   // last of this replay's 256
        }
        __syncthreads();

        if (s_last) {
            __threadfence();
            if (warp == 0) {
                float v = 0.f;
                #pragma unroll
                for (int j = 0; j < 8; ++j)
                    v += g_lossp[lane + 32 * j];
                #pragma unroll
                for (int off = 16; off > 0; off >>= 1)
                    v += __shfl_xor_sync(0xFFFFFFFFu, v, off);
                if (lane == 0) out[0] = v * (1.f / (float)B_);
            }
        }
    }
}

// ============================================================
// launch: 2 kernels, serial
// ============================================================
extern "C" void kernel_launch(void* const* d_in, const int* in_sizes, int n_in,
                              void* d_out, int out_size)
{
    const int*   tokens  = (const int*)d_in[0];
    const int*   lengths = (const int*)d_in[1];
    const float* t       = (const float*)d_in[2];
    const float* emb     = (const float*)d_in[3];
    const float* W1      = (const float*)d_in[4];
    const float* b1      = (const float*)d_in[5];
    const float* gamma   = (const float*)d_in[6];
    const float* beta    = (const float*)d_in[7];
    const float* w2      = (const float*)d_in[8];
    const float* b2      = (const float*)d_in[9];
    float* out = (float*)d_out;

    float* z; cudaGetSymbolAddress((void**)&z, g_z);

    pool_kernel<<<B_ * 2, 64>>>(tokens, lengths, emb);

    gemm_head_kernel<<<NB, 256>>>(lengths, W1, b1, gamma, beta, w2, b2, t,
                                  z, out);
}